// round 7
// baseline (speedup 1.0000x reference)
#include <cuda_runtime.h>
#include <math.h>

#define N_NODES 150000
#define D 100
#define T_STEPS 16
#define E_EDGES 262144          // 2^18
#define E_SHIFT 18
#define S_SEEDS 4096
#define K_CAND 9
#define G4 400                  // 4*D gates
#define KDIM 200                // concat(x, h_prev)
#define LDP 68                  // padded smem stride for GEMM tiles
#define SMEM_GEMM (2 * KDIM * LDP * (int)sizeof(float))

#define NT (T_STEPS * N_NODES)  // 2,400,000 histogram bins
#define SCAN_B 512
#define NBLK ((NT + SCAN_B - 1) / SCAN_B)  // 4688

// ---------------- persistent device state (no allocation allowed) ----------
__device__ float g_emb[N_NODES * D];            // ping buffer (60 MB)
__device__ float g_emb2[N_NODES * D];           // pong buffer (60 MB)
__device__ float g_c[N_NODES * D];              // cell state  (60 MB)
__device__ float g_cprev[S_SEEDS * D];          // c[seed] snapshot
__device__ float g_gates[S_SEEDS * G4];         // LSTM pre-activations
__device__ float g_W[G4 * KDIM];                // [W_ih | W_hh]
__device__ float g_b[G4];                       // b_ih + b_hh
__device__ float g_user[T_STEPS * S_SEEDS * D]; // h history (26 MB)

__device__ int g_hist[NT];      // per (t,node) in-degree
__device__ int g_start[NT];     // exclusive scan of g_hist (global positions)
__device__ int g_cur[NT];       // fill cursors
__device__ int g_bsum[NBLK];    // scan partials
__device__ int g_epack[T_STEPS * E_EDGES];  // src | (cat<<18), sorted by (t,dst)

// ---------------- helpers ---------------------------------------------------
__device__ __forceinline__ float sigf(float x) {
    return 1.0f / (1.0f + expf(-x));
}

// ---------------- CSR build -------------------------------------------------
__global__ void k_zero_hist() {
    int i = blockIdx.x * blockDim.x + threadIdx.x;
    if (i < NT / 4) ((int4*)g_hist)[i] = make_int4(0, 0, 0, 0);
}

__global__ void k_hist(const int* __restrict__ dst) {
    int ti = blockIdx.x * blockDim.x + threadIdx.x;
    if (ti >= T_STEPS * E_EDGES) return;
    int bin = (ti >> E_SHIFT) * N_NODES + dst[ti];
    atomicAdd(&g_hist[bin], 1);
}

// exclusive scan, stage 1: per-block (512) scan + block sums
__global__ void k_scan1() {
    __shared__ int sh[SCAN_B];
    int b = blockIdx.x, tid = threadIdx.x;
    int i = b * SCAN_B + tid;
    int v = (i < NT) ? g_hist[i] : 0;
    sh[tid] = v;
    __syncthreads();
#pragma unroll
    for (int off = 1; off < SCAN_B; off <<= 1) {
        int x = (tid >= off) ? sh[tid - off] : 0;
        __syncthreads();
        sh[tid] += x;
        __syncthreads();
    }
    if (i < NT) g_start[i] = sh[tid] - v;       // exclusive within block
    if (tid == SCAN_B - 1) g_bsum[b] = sh[tid]; // block total
}

// stage 2: exclusive scan of block sums (single block, chunked)
__global__ void k_scan2() {
    __shared__ int sh[1024];
    __shared__ int carry_s;
    int tid = threadIdx.x;
    if (tid == 0) carry_s = 0;
    __syncthreads();
    for (int base = 0; base < NBLK; base += 1024) {
        int i = base + tid;
        int v = (i < NBLK) ? g_bsum[i] : 0;
        sh[tid] = v;
        __syncthreads();
#pragma unroll
        for (int off = 1; off < 1024; off <<= 1) {
            int x = (tid >= off) ? sh[tid - off] : 0;
            __syncthreads();
            sh[tid] += x;
            __syncthreads();
        }
        int carry = carry_s;
        if (i < NBLK) g_bsum[i] = sh[tid] - v + carry;
        __syncthreads();
        if (tid == 0) carry_s = carry + sh[1023];
        __syncthreads();
    }
}

// stage 3: add block offsets; init cursors
__global__ void k_scan3() {
    int i = blockIdx.x * blockDim.x + threadIdx.x;
    if (i >= NT) return;
    int s = g_start[i] + g_bsum[i / SCAN_B];
    g_start[i] = s;
    g_cur[i] = s;
}

// bucket fill: place each edge into its (t,dst) segment
__global__ void k_fill(const int* __restrict__ src,
                       const int* __restrict__ dst,
                       const int* __restrict__ cat) {
    int ti = blockIdx.x * blockDim.x + threadIdx.x;
    if (ti >= T_STEPS * E_EDGES) return;
    int bin = (ti >> E_SHIFT) * N_NODES + dst[ti];
    int pos = atomicAdd(&g_cur[bin], 1);
    g_epack[pos] = src[ti] | (cat[ti] << 18);
}

// ---------------- weight prep ------------------------------------------------
__global__ void k_wprep(const float* __restrict__ W_ih,
                        const float* __restrict__ W_hh,
                        const float* __restrict__ b_ih,
                        const float* __restrict__ b_hh) {
    int idx = blockIdx.x * blockDim.x + threadIdx.x;
    if (idx < G4 * KDIM) {
        int g = idx / KDIM, k = idx - g * KDIM;
        g_W[idx] = (k < D) ? W_ih[g * D + k] : W_hh[g * D + (k - D)];
    }
    if (idx < G4) g_b[idx] = b_ih[idx] + b_hh[idx];
}

// ---------------- per-step aggregation (gather, no atomics) ------------------
// emb_new[n] = emb_old[n] + (sum_{e: dst=n} emb_old[src_e] * rel[cat_e]) / deg
__global__ void k_agg(int t, int p, const float* __restrict__ rel) {
    int n = blockIdx.x * 8 + (threadIdx.x >> 5);
    if (n >= N_NODES) return;
    int lane = threadIdx.x & 31;
    if (lane >= D / 4) return;
    const float* ob = p ? g_emb2 : g_emb;
    float*       nb = p ? g_emb  : g_emb2;
    int bin = t * N_NODES + n;
    int deg = g_hist[bin];
    float4 acc = make_float4(0.f, 0.f, 0.f, 0.f);
    if (deg > 0) {
        int base = g_start[bin];
        for (int j = 0; j < deg; j++) {
            int pk = __ldg(&g_epack[base + j]);
            int s = pk & 0x3FFFF;
            int c = pk >> 18;
            float4 a = __ldg(((const float4*)(ob + (long long)s * D)) + lane);
            float4 r = __ldg(((const float4*)(rel + (long long)c * D)) + lane);
            acc.x += a.x * r.x; acc.y += a.y * r.y;
            acc.z += a.z * r.z; acc.w += a.w * r.w;
        }
    }
    float rinv = (deg > 0) ? 1.0f / (float)deg : 0.0f;
    float4 e = ((const float4*)(ob + (long long)n * D))[lane];
    e.x += acc.x * rinv; e.y += acc.y * rinv;
    e.z += acc.z * rinv; e.w += acc.w * rinv;
    ((float4*)(nb + (long long)n * D))[lane] = e;
}

// ---------------- LSTM GEMM: gates = [x|h_prev] @ W^T + b --------------------
// M=4096 seeds, N=400 gates, K=200. 64x64 tile, 128 threads, 8x4 microtile.
// x gathered from emb_new[seed], h_prev from emb_old[seed] (ping-pong).
// blockIdx.y==0 blocks also snapshot c_prev.
__global__ void __launch_bounds__(128) k_gemm(int p, const int* __restrict__ seeds) {
    extern __shared__ float sm[];
    float* As = sm;                 // [KDIM][LDP]
    float* Bs = sm + KDIM * LDP;    // [KDIM][LDP]
    __shared__ int sseed[64];

    const float* ob = p ? g_emb2 : g_emb;
    const float* nb = p ? g_emb  : g_emb2;

    int tid = threadIdx.x;
    int s0 = blockIdx.x * 64;
    int g0 = blockIdx.y * 64;

    if (tid < 64) sseed[tid] = seeds[s0 + tid];
    __syncthreads();

    // A tile: rows = seeds, cols k<100 from emb_new (x), k>=100 from emb_old (h)
    for (int i = tid; i < 64 * (KDIM / 4); i += 128) {
        int r = i / (KDIM / 4), q = i - r * (KDIM / 4);
        int node = sseed[r];
        const float* sp = (q < D / 4)
            ? (nb + (long long)node * D + q * 4)
            : (ob + (long long)node * D + (q - D / 4) * 4);
        float4 v = *(const float4*)sp;
        int k = q * 4;
        As[(k + 0) * LDP + r] = v.x;
        As[(k + 1) * LDP + r] = v.y;
        As[(k + 2) * LDP + r] = v.z;
        As[(k + 3) * LDP + r] = v.w;
    }
    // B tile: rows = gates
    for (int i = tid; i < 64 * (KDIM / 4); i += 128) {
        int r = i / (KDIM / 4), q = i - r * (KDIM / 4);
        int g = g0 + r;
        float4 v = (g < G4) ? *(const float4*)(g_W + (long long)g * KDIM + q * 4)
                            : make_float4(0.f, 0.f, 0.f, 0.f);
        int k = q * 4;
        Bs[(k + 0) * LDP + r] = v.x;
        Bs[(k + 1) * LDP + r] = v.y;
        Bs[(k + 2) * LDP + r] = v.z;
        Bs[(k + 3) * LDP + r] = v.w;
    }
    __syncthreads();

    // c_prev snapshot (only y==0 blocks; values identical across dup seeds)
    if (blockIdx.y == 0) {
        for (int i = tid; i < 64 * D; i += 128) {
            int r = i / D, j = i - r * D;
            g_cprev[(s0 + r) * D + j] = g_c[(long long)sseed[r] * D + j];
        }
    }

    int tx = tid & 15;      // N dir, 4 wide
    int ty = tid >> 4;      // M dir, 8 wide (0..7)

    float acc[8][4];
#pragma unroll
    for (int i = 0; i < 8; i++)
#pragma unroll
        for (int j = 0; j < 4; j++) acc[i][j] = 0.0f;

#pragma unroll 4
    for (int k = 0; k < KDIM; k++) {
        float4 b4 = *(const float4*)(Bs + k * LDP + tx * 4);
        float4 a0 = *(const float4*)(As + k * LDP + ty * 8);
        float4 a1 = *(const float4*)(As + k * LDP + ty * 8 + 4);
        float av[8] = {a0.x, a0.y, a0.z, a0.w, a1.x, a1.y, a1.z, a1.w};
        float bv[4] = {b4.x, b4.y, b4.z, b4.w};
#pragma unroll
        for (int i = 0; i < 8; i++)
#pragma unroll
            for (int j = 0; j < 4; j++) acc[i][j] += av[i] * bv[j];
    }

#pragma unroll
    for (int i = 0; i < 8; i++) {
        int srow = s0 + ty * 8 + i;
#pragma unroll
        for (int j = 0; j < 4; j++) {
            int g = g0 + tx * 4 + j;
            if (g < G4) g_gates[(long long)srow * G4 + g] = acc[i][j] + g_b[g];
        }
    }
}

// ---------------- LSTM pointwise ---------------------------------------------
__global__ void k_point(int p, const int* __restrict__ seeds, int t) {
    int s = blockIdx.x;
    int j = threadIdx.x;
    if (j >= D) return;
    float* nb = p ? g_emb : g_emb2;
    const float* gr = g_gates + (long long)s * G4;
    float ig = gr[j];
    float fg = gr[D + j];
    float gg = gr[2 * D + j];
    float og = gr[3 * D + j];
    float cp = g_cprev[s * D + j];
    float cn = sigf(fg) * cp + sigf(ig) * tanhf(gg);
    float hn = sigf(og) * tanhf(cn);
    long long node = seeds[s];
    nb[node * D + j] = hn;
    g_c[node * D + j] = cn;
    g_user[((long long)t * S_SEEDS + s) * D + j] = hn;
}

// ---------------- scoring ------------------------------------------------------
// scores[n][k] = dot(user[n], emb_final[cand[n][k]]); emb_final = g_emb (T even)
__global__ void k_score(const int* __restrict__ cand,
                        float* __restrict__ out) {
    __shared__ float u[D];
    int n = blockIdx.x;
    int tid = threadIdx.x;
    if (tid < D) u[tid] = g_user[(long long)n * D + tid];
    __syncthreads();
    int w = tid >> 5, lane = tid & 31;
    if (w >= K_CAND) return;
    int cidx = cand[(long long)n * K_CAND + w];
    const float* cr = g_emb + (long long)cidx * D;
    float sum = 0.0f;
    for (int j = lane; j < D; j += 32) sum += u[j] * cr[j];
#pragma unroll
    for (int o = 16; o; o >>= 1) sum += __shfl_down_sync(0xffffffffu, sum, o);
    if (lane == 0) out[(long long)n * K_CAND + w] = sum;
}

// ---------------- host ------------------------------------------------------
extern "C" void kernel_launch(void* const* d_in, const int* in_sizes, int n_in,
                              void* d_out, int out_size) {
    const float* node_emb = (const float*)d_in[0];
    const float* cx       = (const float*)d_in[1];
    const float* rel      = (const float*)d_in[2];
    const float* W_ih     = (const float*)d_in[3];
    const float* W_hh     = (const float*)d_in[4];
    const float* b_ih     = (const float*)d_in[5];
    const float* b_hh     = (const float*)d_in[6];
    const int* src   = (const int*)d_in[7];
    const int* dst   = (const int*)d_in[8];
    const int* cat   = (const int*)d_in[9];
    const int* seeds = (const int*)d_in[10];
    const int* cand  = (const int*)d_in[11];
    float* out = (float*)d_out;

    (void)in_sizes; (void)n_in; (void)out_size;

    cudaFuncSetAttribute(k_gemm, cudaFuncAttributeMaxDynamicSharedMemorySize,
                         SMEM_GEMM);

    // reset mutable state from inputs (graph-replay deterministic)
    cudaMemcpyToSymbolAsync(g_emb, node_emb, sizeof(float) * N_NODES * D, 0,
                            cudaMemcpyDeviceToDevice, 0);
    cudaMemcpyToSymbolAsync(g_c, cx, sizeof(float) * N_NODES * D, 0,
                            cudaMemcpyDeviceToDevice, 0);

    // weights + CSR build (edge layout is per-call input, rebuilt every call)
    k_wprep<<<(G4 * KDIM + 255) / 256, 256>>>(W_ih, W_hh, b_ih, b_hh);
    k_zero_hist<<<(NT / 4 + 255) / 256, 256>>>();
    int te = T_STEPS * E_EDGES;
    k_hist<<<(te + 255) / 256, 256>>>(dst);
    k_scan1<<<NBLK, SCAN_B>>>();
    k_scan2<<<1, 1024>>>();
    k_scan3<<<(NT + 255) / 256, 256>>>();
    k_fill<<<(te + 255) / 256, 256>>>(src, dst, cat);

    for (int t = 0; t < T_STEPS; t++) {
        int p = t & 1;  // p==0: old=g_emb, new=g_emb2; p==1: reversed
        const int* seeds_t = seeds + (long long)t * S_SEEDS;
        k_agg<<<(N_NODES + 7) / 8, 256>>>(t, p, rel);
        k_gemm<<<dim3(S_SEEDS / 64, (G4 + 63) / 64), 128, SMEM_GEMM>>>(p, seeds_t);
        k_point<<<S_SEEDS, 128>>>(p, seeds_t, t);
    }

    // T even -> final embeddings live in g_emb
    k_score<<<T_STEPS * S_SEEDS, 288>>>(cand, out);
}

// round 8
// speedup vs baseline: 1.1264x; 1.1264x over previous
#include <cuda_runtime.h>
#include <math.h>

#define N_NODES 150000
#define D 100
#define T_STEPS 16
#define E_EDGES 262144          // 2^18
#define E_SHIFT 18
#define S_SEEDS 4096
#define K_CAND 9
#define G4 400                  // 4*D gates
#define KDIM 200                // concat(x, h_prev)
#define LDP 68                  // padded smem stride for GEMM tiles
#define SMEM_GEMM (2 * KDIM * LDP * (int)sizeof(float))

#define NT (T_STEPS * N_NODES)          // 2,400,000 bins
#define TE (T_STEPS * E_EDGES)          // 4,194,304 edges
#define SCAN_ELEMS 1024                 // elems per scan1 block (256 thr x int4)
#define NBLK ((NT + SCAN_ELEMS - 1) / SCAN_ELEMS)  // 2344

// ---------------- persistent device state (no allocation allowed) ----------
__device__ float g_emb[N_NODES * D];            // ping buffer (60 MB)
__device__ float g_emb2[N_NODES * D];           // pong buffer (60 MB)
__device__ float g_c[N_NODES * D];              // lazy cell state (60 MB)
__device__ int   g_cstamp[N_NODES];             // 0 => c == cx (zero-init)
__device__ float g_cprev[S_SEEDS * D];          // c[seed] snapshot
__device__ float g_gates[S_SEEDS * G4];         // LSTM pre-activations
__device__ float g_W[G4 * KDIM];                // [W_ih | W_hh]
__device__ float g_b[G4];                       // b_ih + b_hh
__device__ float g_user[T_STEPS * S_SEEDS * D]; // h history (26 MB)

__device__ int g_hist[NT];        // per (t,node) in-degree (zero-init; cleared in scan1)
__device__ int g_start[NT + 4];   // exclusive scan (+ sentinel at [NT])
__device__ int g_cur[NT];         // fill cursors
__device__ int g_bsum[NBLK];      // scan partials
__device__ int g_epack[TE];       // src | (cat<<18), grouped by (t,dst)

// ---------------- helpers ---------------------------------------------------
__device__ __forceinline__ float sigf(float x) {
    return 1.0f / (1.0f + expf(-x));
}

// ---------------- CSR build -------------------------------------------------
__global__ void k_hist(const int* __restrict__ dst) {
    int ti = blockIdx.x * blockDim.x + threadIdx.x;
    if (ti >= TE) return;
    int bin = (ti >> E_SHIFT) * N_NODES + dst[ti];
    atomicAdd(&g_hist[bin], 1);
}

// scan stage 1: each block scans 1024 elems (int4 per thread), zeros hist,
// writes within-block exclusive scan to g_start and block total to g_bsum.
__global__ void __launch_bounds__(256) k_scan1() {
    __shared__ int wsum[8];
    int b = blockIdx.x, tid = threadIdx.x;
    int lane = tid & 31, w = tid >> 5;
    int gi = b * 256 + tid;                      // int4 index
    int4 v = make_int4(0, 0, 0, 0);
    if (gi < NT / 4) {
        v = ((int4*)g_hist)[gi];
        ((int4*)g_hist)[gi] = make_int4(0, 0, 0, 0);  // pre-clear for next call
    }
    int s = v.x + v.y + v.z + v.w;
    int inc = s;
#pragma unroll
    for (int off = 1; off < 32; off <<= 1) {
        int x = __shfl_up_sync(0xffffffffu, inc, off);
        if (lane >= off) inc += x;
    }
    if (lane == 31) wsum[w] = inc;
    __syncthreads();
    if (w == 0) {
        int ws = (lane < 8) ? wsum[lane] : 0;
#pragma unroll
        for (int off = 1; off < 8; off <<= 1) {
            int x = __shfl_up_sync(0xffffffffu, ws, off);
            if (lane >= off) ws += x;
        }
        if (lane < 8) wsum[lane] = ws;
    }
    __syncthreads();
    int base = inc - s + (w > 0 ? wsum[w - 1] : 0);
    if (gi < NT / 4) {
        int4 o;
        o.x = base;
        o.y = base + v.x;
        o.z = o.y + v.y;
        o.w = o.z + v.z;
        ((int4*)g_start)[gi] = o;
    }
    if (tid == 0) g_bsum[b] = 0;  // will be overwritten below; keeps lastblk sane
    __syncthreads();
    if (tid == 255) g_bsum[b] = wsum[7];
}

// scan stage 2: exclusive scan of NBLK block sums (single block, shfl-based)
__global__ void __launch_bounds__(1024) k_scan2() {
    __shared__ int wsum[32];
    __shared__ int carry;
    int tid = threadIdx.x;
    int lane = tid & 31, w = tid >> 5;
    if (tid == 0) carry = 0;
    __syncthreads();
    for (int base = 0; base < NBLK; base += 1024) {
        int i = base + tid;
        int v = (i < NBLK) ? g_bsum[i] : 0;
        int inc = v;
#pragma unroll
        for (int off = 1; off < 32; off <<= 1) {
            int x = __shfl_up_sync(0xffffffffu, inc, off);
            if (lane >= off) inc += x;
        }
        if (lane == 31) wsum[w] = inc;
        __syncthreads();
        if (w == 0) {
            int ws = wsum[lane];
#pragma unroll
            for (int off = 1; off < 32; off <<= 1) {
                int x = __shfl_up_sync(0xffffffffu, ws, off);
                if (lane >= off) ws += x;
            }
            wsum[lane] = ws;
        }
        __syncthreads();
        int ex = inc - v + (w > 0 ? wsum[w - 1] : 0) + carry;
        if (i < NBLK) g_bsum[i] = ex;
        __syncthreads();
        if (tid == 0) carry += wsum[31];
        __syncthreads();
    }
}

// scan stage 3: add block offsets; init cursors; set sentinel
__global__ void k_scan3() {
    int gi = blockIdx.x * blockDim.x + threadIdx.x;   // int4 index
    if (gi < NT / 4) {
        int add = g_bsum[gi >> 8];                    // 256 int4 per scan1 block
        int4 s = ((int4*)g_start)[gi];
        s.x += add; s.y += add; s.z += add; s.w += add;
        ((int4*)g_start)[gi] = s;
        ((int4*)g_cur)[gi] = s;
    }
    if (gi == 0) g_start[NT] = TE;
}

// bucket fill: place each edge into its (t,dst) segment
__global__ void k_fill(const int* __restrict__ src,
                       const int* __restrict__ dst,
                       const int* __restrict__ cat) {
    int ti = blockIdx.x * blockDim.x + threadIdx.x;
    if (ti >= TE) return;
    int bin = (ti >> E_SHIFT) * N_NODES + dst[ti];
    int pos = atomicAdd(&g_cur[bin], 1);
    g_epack[pos] = src[ti] | (cat[ti] << 18);
}

// ---------------- weight prep ------------------------------------------------
__global__ void k_wprep(const float* __restrict__ W_ih,
                        const float* __restrict__ W_hh,
                        const float* __restrict__ b_ih,
                        const float* __restrict__ b_hh) {
    int idx = blockIdx.x * blockDim.x + threadIdx.x;
    if (idx < G4 * KDIM) {
        int g = idx / KDIM, k = idx - g * KDIM;
        g_W[idx] = (k < D) ? W_ih[g * D + k] : W_hh[g * D + (k - D)];
    }
    if (idx < G4) g_b[idx] = b_ih[idx] + b_hh[idx];
}

// ---------------- per-step aggregation (gather, no atomics) ------------------
// nb[n] = ob[n] + (sum_{e: dst=n} ob[src_e] * rel[cat_e]) / deg
__global__ void __launch_bounds__(256) k_agg(int t,
                                             const float* __restrict__ ob,
                                             float* __restrict__ nb,
                                             const float* __restrict__ rel) {
    int n = blockIdx.x * 8 + (threadIdx.x >> 5);
    if (n >= N_NODES) return;
    int lane = threadIdx.x & 31;
    int bin = t * N_NODES + n;
    int s0 = __ldg(&g_start[bin]);
    int s1 = __ldg(&g_start[bin + 1]);
    int deg = s1 - s0;

    float4 acc = make_float4(0.f, 0.f, 0.f, 0.f);
    for (int j0 = 0; j0 < deg; j0 += 32) {
        int m = deg - j0;
        if (m > 32) m = 32;
        int pk = (lane < m) ? __ldg(&g_epack[s0 + j0 + lane]) : 0;
#pragma unroll 4
        for (int j = 0; j < m; j++) {
            int p = __shfl_sync(0xffffffffu, pk, j);
            if (lane < D / 4) {
                int s = p & 0x3FFFF;
                int c = p >> 18;
                float4 a = __ldg(((const float4*)ob) + s * (D / 4) + lane);
                float4 r = __ldg(((const float4*)rel) + c * (D / 4) + lane);
                acc.x = fmaf(a.x, r.x, acc.x);
                acc.y = fmaf(a.y, r.y, acc.y);
                acc.z = fmaf(a.z, r.z, acc.z);
                acc.w = fmaf(a.w, r.w, acc.w);
            }
        }
    }
    if (lane < D / 4) {
        float4 e = __ldg(((const float4*)ob) + n * (D / 4) + lane);
        if (deg > 0) {
            float invd = 1.0f / (float)deg;
            e.x += acc.x * invd;
            e.y += acc.y * invd;
            e.z += acc.z * invd;
            e.w += acc.w * invd;
        }
        ((float4*)nb)[n * (D / 4) + lane] = e;
    }
}

// ---------------- LSTM GEMM: gates = [x|h_prev] @ W^T + b --------------------
// M=4096 seeds, N=400 gates, K=200. 64x64 tile, 128 threads, 8x4 microtile.
// x from nb[seed] (post-agg), h_prev from ob[seed] (pre-agg).
// blockIdx.y==0 blocks also snapshot c_prev (lazy c via stamp).
__global__ void __launch_bounds__(128) k_gemm(const float* __restrict__ ob,
                                              const float* __restrict__ nb,
                                              const float* __restrict__ cx,
                                              const int* __restrict__ seeds) {
    extern __shared__ float sm[];
    float* As = sm;                 // [KDIM][LDP]
    float* Bs = sm + KDIM * LDP;    // [KDIM][LDP]
    __shared__ int sseed[64];

    int tid = threadIdx.x;
    int s0 = blockIdx.x * 64;
    int g0 = blockIdx.y * 64;

    if (tid < 64) sseed[tid] = seeds[s0 + tid];
    __syncthreads();

    // A tile: rows = seeds, k<100 from nb (x), k>=100 from ob (h_prev)
    for (int i = tid; i < 64 * (KDIM / 4); i += 128) {
        int r = i / (KDIM / 4), q = i - r * (KDIM / 4);
        int node = sseed[r];
        const float* sp = (q < D / 4)
            ? (nb + node * D + q * 4)
            : (ob + node * D + (q - D / 4) * 4);
        float4 v = *(const float4*)sp;
        int k = q * 4;
        As[(k + 0) * LDP + r] = v.x;
        As[(k + 1) * LDP + r] = v.y;
        As[(k + 2) * LDP + r] = v.z;
        As[(k + 3) * LDP + r] = v.w;
    }
    // B tile: rows = gates
    for (int i = tid; i < 64 * (KDIM / 4); i += 128) {
        int r = i / (KDIM / 4), q = i - r * (KDIM / 4);
        int g = g0 + r;
        float4 v = (g < G4) ? *(const float4*)(g_W + g * KDIM + q * 4)
                            : make_float4(0.f, 0.f, 0.f, 0.f);
        int k = q * 4;
        Bs[(k + 0) * LDP + r] = v.x;
        Bs[(k + 1) * LDP + r] = v.y;
        Bs[(k + 2) * LDP + r] = v.z;
        Bs[(k + 3) * LDP + r] = v.w;
    }
    __syncthreads();

    // c_prev snapshot (y==0 blocks; identical values for duplicate seeds)
    if (blockIdx.y == 0) {
        for (int i = tid; i < 64 * D; i += 128) {
            int r = i / D, j = i - r * D;
            int node = sseed[r];
            float cp = g_cstamp[node] ? g_c[node * D + j] : cx[node * D + j];
            g_cprev[(s0 + r) * D + j] = cp;
        }
    }

    int tx = tid & 15;      // N dir (4 wide)
    int ty = tid >> 4;      // M dir (8 wide)

    float acc[8][4];
#pragma unroll
    for (int i = 0; i < 8; i++)
#pragma unroll
        for (int j = 0; j < 4; j++) acc[i][j] = 0.0f;

#pragma unroll 4
    for (int k = 0; k < KDIM; k++) {
        float4 b4 = *(const float4*)(Bs + k * LDP + tx * 4);
        float4 a0 = *(const float4*)(As + k * LDP + ty * 8);
        float4 a1 = *(const float4*)(As + k * LDP + ty * 8 + 4);
        float av[8] = {a0.x, a0.y, a0.z, a0.w, a1.x, a1.y, a1.z, a1.w};
        float bv[4] = {b4.x, b4.y, b4.z, b4.w};
#pragma unroll
        for (int i = 0; i < 8; i++)
#pragma unroll
            for (int j = 0; j < 4; j++) acc[i][j] += av[i] * bv[j];
    }

#pragma unroll
    for (int i = 0; i < 8; i++) {
        int srow = s0 + ty * 8 + i;
#pragma unroll
        for (int j = 0; j < 4; j++) {
            int g = g0 + tx * 4 + j;
            if (g < G4) g_gates[srow * G4 + g] = acc[i][j] + g_b[g];
        }
    }
}

// ---------------- LSTM pointwise ---------------------------------------------
__global__ void k_point(float* __restrict__ nb,
                        const int* __restrict__ seeds, int t) {
    int s = blockIdx.x;
    int j = threadIdx.x;
    if (j >= D) return;
    const float* gr = g_gates + s * G4;
    float ig = gr[j];
    float fg = gr[D + j];
    float gg = gr[2 * D + j];
    float og = gr[3 * D + j];
    float cp = g_cprev[s * D + j];
    float cn = sigf(fg) * cp + sigf(ig) * tanhf(gg);
    float hn = sigf(og) * tanhf(cn);
    int node = seeds[s];
    nb[node * D + j] = hn;
    g_c[node * D + j] = cn;
    if (j == 0) g_cstamp[node] = 1;
    g_user[(t * S_SEEDS + s) * D + j] = hn;
}

// ---------------- scoring ------------------------------------------------------
__global__ void k_score(const float* __restrict__ emb_final,
                        const int* __restrict__ cand,
                        float* __restrict__ out) {
    __shared__ float u[D];
    int n = blockIdx.x;
    int tid = threadIdx.x;
    if (tid < D) u[tid] = g_user[n * D + tid];
    __syncthreads();
    int w = tid >> 5, lane = tid & 31;
    if (w >= K_CAND) return;
    int cidx = cand[n * K_CAND + w];
    const float* cr = emb_final + cidx * D;
    float sum = 0.0f;
    for (int j = lane; j < D; j += 32) sum += u[j] * cr[j];
#pragma unroll
    for (int o = 16; o; o >>= 1) sum += __shfl_down_sync(0xffffffffu, sum, o);
    if (lane == 0) out[n * K_CAND + w] = sum;
}

// tail: restore stamp invariants for next graph replay
__global__ void k_clean(const int* __restrict__ seeds) {
    int i = blockIdx.x * blockDim.x + threadIdx.x;
    if (i < T_STEPS * S_SEEDS) g_cstamp[seeds[i]] = 0;
}

// ---------------- host ------------------------------------------------------
extern "C" void kernel_launch(void* const* d_in, const int* in_sizes, int n_in,
                              void* d_out, int out_size) {
    const float* node_emb = (const float*)d_in[0];
    const float* cx       = (const float*)d_in[1];
    const float* rel      = (const float*)d_in[2];
    const float* W_ih     = (const float*)d_in[3];
    const float* W_hh     = (const float*)d_in[4];
    const float* b_ih     = (const float*)d_in[5];
    const float* b_hh     = (const float*)d_in[6];
    const int* src   = (const int*)d_in[7];
    const int* dst   = (const int*)d_in[8];
    const int* cat   = (const int*)d_in[9];
    const int* seeds = (const int*)d_in[10];
    const int* cand  = (const int*)d_in[11];
    float* out = (float*)d_out;

    (void)in_sizes; (void)n_in; (void)out_size;

    cudaFuncSetAttribute(k_gemm, cudaFuncAttributeMaxDynamicSharedMemorySize,
                         SMEM_GEMM);

    // pointers to device symbols (host-side address resolution)
    float *p_emb = nullptr, *p_emb2 = nullptr;
    cudaGetSymbolAddress((void**)&p_emb, g_emb);
    cudaGetSymbolAddress((void**)&p_emb2, g_emb2);

    // weights + CSR build (g_hist is zero on entry: zero-init at load,
    // re-cleared inside k_scan1 every call)
    k_wprep<<<(G4 * KDIM + 255) / 256, 256>>>(W_ih, W_hh, b_ih, b_hh);
    k_hist<<<(TE + 255) / 256, 256>>>(dst);
    k_scan1<<<NBLK, 256>>>();
    k_scan2<<<1, 1024>>>();
    k_scan3<<<(NT / 4 + 255) / 256, 256>>>();
    k_fill<<<(TE + 255) / 256, 256>>>(src, dst, cat);

    for (int t = 0; t < T_STEPS; t++) {
        const float* ob = (t == 0) ? node_emb : ((t & 1) ? p_emb : p_emb2);
        float* nb = (t & 1) ? p_emb2 : p_emb;
        const int* seeds_t = seeds + t * S_SEEDS;
        k_agg<<<(N_NODES + 7) / 8, 256>>>(t, ob, nb, rel);
        k_gemm<<<dim3(S_SEEDS / 64, (G4 + 63) / 64), 128, SMEM_GEMM>>>(
            ob, nb, cx, seeds_t);
        k_point<<<S_SEEDS, 128>>>(nb, seeds_t, t);
    }

    // final embeddings: t=15 wrote g_emb2
    k_score<<<T_STEPS * S_SEEDS, 288>>>(p_emb2, cand, out);
    k_clean<<<(T_STEPS * S_SEEDS + 255) / 256, 256>>>(seeds);
}